// round 17
// baseline (speedup 1.0000x reference)
#include <cuda_runtime.h>
#include <cuda_bf16.h>
#include <cstdint>

#define D        32
#define HID      128
#define GRID_G   64
#define NN       4096
#define BB       8
#define TOTAL    (BB*NN)   // 32768 nodes
#define ROW      80
#define MT       64        // nodes per CTA
#define NCTA     (TOTAL/MT) // 512 -> single wave

// ---- smem byte offsets (overlayed phases) ----
#define XH_OFF   0          // X hi  [64 rows x 144B]
#define XL_OFF   9216       // X lo
#define W1H_OFF  18432      // W1^T hi [128 x 144B]
#define W1L_OFF  36864      // W1^T lo
// phase 2 overlays (X/W1 dead after GEMM1):
#define HH_OFF   0          // H hi [64 x 272B]
#define HL_OFF   17408      // H lo
#define W2H_OFF  34816      // W2^T hi [32 x 272B]
#define W2L_OFF  43520      // W2^T lo
#define SMEM_BYTES 55296
#define XSTR     144
#define W1STR    144
#define HSTR     272
#define W2STR    272

#define W1IMG_BYTES 36864
#define W2IMG_BYTES 17408

// xi-contribution scratch: C[net][node][j] (includes b1)
__device__ float g_C[2][TOTAL * HID];
// pre-split bf16 weight images (byte-identical to smem regions)
__device__ __align__(16) unsigned char g_W1img[2][W1IMG_BYTES];
__device__ __align__(16) unsigned char g_W2img[2][W2IMG_BYTES];

// ---- packed f32x2 helpers (precompute kernel only) ----
#define FMA2(d, a, b, c) \
    asm("fma.rn.f32x2 %0, %1, %2, %3;" : "=l"(d) : "l"(a), "l"(b), "l"(c))
#define ADD2(d, a, b) \
    asm("add.rn.f32x2 %0, %1, %2;" : "=l"(d) : "l"(a), "l"(b))
#define PACK2(d, lo, hi) \
    asm("mov.b64 %0, {%1, %2};" : "=l"(d) : "f"(lo), "f"(hi))
#define UNPACK2(lo, hi, s) \
    asm("mov.b64 {%0, %1}, %2;" : "=f"(lo), "=f"(hi) : "l"(s))

__device__ __forceinline__ float tanh_fast(float x) {
    float e = __expf(x + x);
    return 1.0f - __fdividef(2.0f, e + 1.0f);
}

__device__ __forceinline__ void mma_bf16(float c[4], const uint32_t a[4],
                                         const uint32_t b[2])
{
    asm volatile(
        "mma.sync.aligned.m16n8k16.row.col.f32.bf16.bf16.f32 "
        "{%0,%1,%2,%3}, {%4,%5,%6,%7}, {%8,%9}, {%0,%1,%2,%3};"
        : "+f"(c[0]), "+f"(c[1]), "+f"(c[2]), "+f"(c[3])
        : "r"(a[0]), "r"(a[1]), "r"(a[2]), "r"(a[3]),
          "r"(b[0]), "r"(b[1]));
}

__device__ __forceinline__ void ldmx4(uint32_t r[4], uint32_t addr) {
    asm volatile(
        "ldmatrix.sync.aligned.m8n8.x4.shared.b16 {%0,%1,%2,%3}, [%4];"
        : "=r"(r[0]), "=r"(r[1]), "=r"(r[2]), "=r"(r[3]) : "r"(addr));
}
__device__ __forceinline__ void ldmx2(uint32_t r[2], uint32_t addr) {
    asm volatile(
        "ldmatrix.sync.aligned.m8n8.x2.shared.b16 {%0,%1}, [%2];"
        : "=r"(r[0]), "=r"(r[1]) : "r"(addr));
}

#define CPA16(dst, src) \
    asm volatile("cp.async.cg.shared.global [%0], [%1], 16;" \
        :: "r"(dst), "l"(src) : "memory")
#define CPA_COMMIT() asm volatile("cp.async.commit_group;" ::: "memory")
#define CPA_WAIT0()  asm volatile("cp.async.wait_group 0;" ::: "memory")

__device__ __forceinline__ uint32_t smem_u32(const void* p) {
    uint32_t a;
    asm("{ .reg .u64 t; cvta.to.shared.u64 t, %1; cvt.u32.u64 %0, t; }"
        : "=r"(a) : "l"(p));
    return a;
}

__device__ __forceinline__ uint32_t split_pack(float a, float b, uint32_t& lo32)
{
    __nv_bfloat16 ah = __float2bfloat16(a);
    __nv_bfloat16 bh = __float2bfloat16(b);
    __nv_bfloat162 hi(ah, bh);
    __nv_bfloat162 lo(__float2bfloat16(a - __bfloat162float(ah)),
                      __float2bfloat16(b - __bfloat162float(bh)));
    lo32 = *reinterpret_cast<uint32_t*>(&lo);
    return *reinterpret_cast<uint32_t*>(&hi);
}

__device__ __forceinline__ void sts_split(char* sm, int hioff, int looff,
                                          float a, float b)
{
    uint32_t lo32, hi32 = split_pack(a, b, lo32);
    *reinterpret_cast<uint32_t*>(sm + hioff) = hi32;
    *reinterpret_cast<uint32_t*>(sm + looff) = lo32;
}

// ---------------------------------------------------------------------------
// Precompute C[which][n][j] = b1[j] + sum_k xi[n][k] * W1[64+k][j]  (fp32).
// Both nets in ONE launch: grid 512; blockIdx.x >> 8 selects the net.
// ---------------------------------------------------------------------------
__global__ void __launch_bounds__(128)
precompute_C_kernel(const float* __restrict__ x,
                    const float* __restrict__ W1q,
                    const float* __restrict__ b1q,
                    const float* __restrict__ W1p,
                    const float* __restrict__ b1p)
{
    const int which = blockIdx.x >> 8;
    const float* W1 = which ? W1p : W1q;
    const float* b1 = which ? b1p : b1q;

    __shared__ float W1cs[16 * HID];
    __shared__ float b1s[HID];
    const int tid = threadIdx.x;
    for (int idx = tid; idx < 16 * HID; idx += 128) {
        int k = idx >> 7, j = idx & 127;
        W1cs[j * 16 + k] = W1[(64 + k) * HID + j];
    }
    if (tid < HID) b1s[tid] = b1[tid];
    __syncthreads();

    const int n = (blockIdx.x & 255) * 128 + tid;
    const float4* xiv = (const float4*)(x + (size_t)n * ROW + 2 * D);
    unsigned long long xp8[8];
    #pragma unroll
    for (int i = 0; i < 4; i++) {
        float4 v = xiv[i];
        PACK2(xp8[2 * i],     v.x, v.y);
        PACK2(xp8[2 * i + 1], v.z, v.w);
    }
    float* Crow = g_C[which] + (size_t)n * HID;
    for (int jb = 0; jb < 32; jb++) {
        float s[4];
        #pragma unroll
        for (int jj = 0; jj < 4; jj++) {
            int j = jb * 4 + jj;
            const ulonglong2* wp = (const ulonglong2*)(W1cs + j * 16);
            unsigned long long a0 = 0ull, a1 = 0ull;
            #pragma unroll
            for (int u = 0; u < 4; u++) {
                ulonglong2 w = wp[u];
                FMA2(a0, xp8[2 * u],     w.x, a0);
                FMA2(a1, xp8[2 * u + 1], w.y, a1);
            }
            ADD2(a0, a0, a1);
            float lo, hi;
            UNPACK2(lo, hi, a0);
            s[jj] = lo + hi + b1s[j];
        }
        *(float4*)(Crow + jb * 4) = make_float4(s[0], s[1], s[2], s[3]);
    }
}

// ---------------------------------------------------------------------------
// Setup: pre-split W1/W2 into bf16 hi/lo byte-images of the smem regions.
// ---------------------------------------------------------------------------
__global__ void __launch_bounds__(128)
setup_weights(const float* __restrict__ W1q, const float* __restrict__ W2q,
              const float* __restrict__ W1p, const float* __restrict__ W2p)
{
    const int which = blockIdx.x;
    const float* W1 = which ? W1p : W1q;
    const float* W2 = which ? W2p : W2q;
    const int tid = threadIdx.x;

    char* im1 = (char*)g_W1img[which];
    #pragma unroll 4
    for (int k2 = 0; k2 < 32; k2++) {
        float a = __ldg(W1 + (2 * k2) * HID + tid);
        float b = __ldg(W1 + (2 * k2 + 1) * HID + tid);
        uint32_t lo32, hi32 = split_pack(a, b, lo32);
        *(uint32_t*)(im1 + tid * W1STR + k2 * 4) = hi32;
        *(uint32_t*)(im1 + 18432 + tid * W1STR + k2 * 4) = lo32;
    }
    char* im2 = (char*)g_W2img[which];
    const int d_ = tid & 31;
    const int j2b = (tid >> 5) * 16;
    #pragma unroll 4
    for (int jj = 0; jj < 16; jj++) {
        int j2 = j2b + jj;
        float a = __ldg(W2 + (2 * j2) * D + d_);
        float b = __ldg(W2 + (2 * j2 + 1) * D + d_);
        uint32_t lo32, hi32 = split_pack(a, b, lo32);
        *(uint32_t*)(im2 + d_ * W2STR + j2 * 4) = hi32;
        *(uint32_t*)(im2 + 8704 + d_ * W2STR + j2 * 4) = lo32;
    }
}

// ---------------------------------------------------------------------------
// Half-step via warp MMA; C preloaded directly into the MMA accumulators.
// ---------------------------------------------------------------------------
__global__ void __launch_bounds__(128, 4)
half_step_mma(float* __restrict__ state,
              const float* __restrict__ tfin,
              const float* __restrict__ b2,   // (32)
              int which, int zoff, int toff,
              float tstart, float dtmax)
{
    extern __shared__ char sm[];
    const uint32_t smb = smem_u32(sm);
    const int tid  = threadIdx.x;
    const int wid  = tid >> 5;
    const int lane = tid & 31;
    const int lr   = lane >> 2;    // 0..7
    const int lq   = lane & 3;     // 0..3
    const int node_base = blockIdx.x * MT;
    const int n0 = wid * 32;

    // ---- stage W1 image via cp.async (overlaps everything below) ----
    {
        const char* src = (const char*)g_W1img[which];
        #pragma unroll
        for (int i = 0; i < W1IMG_BYTES / 16 / 128; i++) {
            int off = (i * 128 + tid) * 16;
            CPA16(smb + W1H_OFF + off, src + off);
        }
        CPA_COMMIT();
    }

    // ---- preload C into MMA accumulators (latency hidden by gather+sync) ----
    float acc[4][4][4];
    {
        #pragma unroll
        for (int mf = 0; mf < 4; mf++) {
            int r_ = mf * 16 + lr;
            const float* Crow0 = g_C[which] + (size_t)(node_base + r_) * HID;
            const float* Crow1 = Crow0 + 8 * HID;
            #pragma unroll
            for (int nf = 0; nf < 4; nf++) {
                int j = n0 + nf * 8 + lq * 2;
                float2 c01 = __ldg((const float2*)(Crow0 + j));
                float2 c23 = __ldg((const float2*)(Crow1 + j));
                acc[mf][nf][0] = c01.x;
                acc[mf][nf][1] = c01.y;
                acc[mf][nf][2] = c23.x;
                acc[mf][nf][3] = c23.y;
            }
        }
    }

    // ---- gather X = [z(32) | mean_nbr(32)], split hi/lo (2 thr/node) ----
    {
        const int n = tid >> 1, half = tid & 1;
        const int node = node_base + n;
        const int nn_ = node & (NN - 1);
        const int r = nn_ >> 6, c = nn_ & (GRID_G - 1);
        const float* bp = state + (size_t)(node - nn_) * ROW;
        float v[32];
        if (half == 0) {
            const float4* pZ = (const float4*)(bp + (size_t)nn_ * ROW + zoff);
            #pragma unroll
            for (int i = 0; i < 8; i++) {
                float4 o = __ldg(pZ + i);
                v[4 * i] = o.x; v[4 * i + 1] = o.y;
                v[4 * i + 2] = o.z; v[4 * i + 3] = o.w;
            }
        } else {
            const int nu = (((r + GRID_G - 1) & (GRID_G - 1)) << 6) | c;
            const int nd = (((r + 1) & (GRID_G - 1)) << 6) | c;
            const int nl = (r << 6) | ((c + GRID_G - 1) & (GRID_G - 1));
            const int nr = (r << 6) | ((c + 1) & (GRID_G - 1));
            const float4* pU = (const float4*)(bp + (size_t)nu * ROW + zoff);
            const float4* pD = (const float4*)(bp + (size_t)nd * ROW + zoff);
            const float4* pL = (const float4*)(bp + (size_t)nl * ROW + zoff);
            const float4* pR = (const float4*)(bp + (size_t)nr * ROW + zoff);
            #pragma unroll
            for (int i = 0; i < 8; i++) {
                float4 a = __ldg(pU + i), b = __ldg(pD + i);
                float4 e = __ldg(pL + i), f = __ldg(pR + i);
                v[4 * i]     = 0.25f * (a.x + b.x + e.x + f.x);
                v[4 * i + 1] = 0.25f * (a.y + b.y + e.y + f.y);
                v[4 * i + 2] = 0.25f * (a.z + b.z + e.z + f.z);
                v[4 * i + 3] = 0.25f * (a.w + b.w + e.w + f.w);
            }
        }
        #pragma unroll
        for (int i = 0; i < 16; i++)
            sts_split(sm, XH_OFF + n * XSTR + half * 64 + i * 4,
                          XL_OFF + n * XSTR + half * 64 + i * 4,
                          v[2 * i], v[2 * i + 1]);
    }
    CPA_WAIT0();
    __syncthreads();

    // ---- GEMM1: per warp M64 x N32 (n0) x K64, 3-product split ----
    const uint32_t aLane = (uint32_t)((lane & 15) * XSTR + (lane >> 4) * 16);
    const uint32_t bLane = (uint32_t)((lane & 7) * W1STR + ((lane >> 3) & 1) * 16);

    #pragma unroll
    for (int kf = 0; kf < 4; kf++) {
        uint32_t ah[4][4], al[4][4];
        #pragma unroll
        for (int mf = 0; mf < 4; mf++) {
            uint32_t base = smb + mf * 16 * XSTR + kf * 32 + aLane;
            ldmx4(ah[mf], base + XH_OFF);
            ldmx4(al[mf], base + XL_OFF);
        }
        #pragma unroll
        for (int nf = 0; nf < 4; nf++) {
            uint32_t bb = smb + (n0 + nf * 8) * W1STR + kf * 32 + bLane;
            uint32_t bh[2], bl[2];
            ldmx2(bh, bb + W1H_OFF);
            ldmx2(bl, bb + W1L_OFF);
            #pragma unroll
            for (int mf = 0; mf < 4; mf++) {
                mma_bf16(acc[mf][nf], ah[mf], bh);
                mma_bf16(acc[mf][nf], al[mf], bh);
                mma_bf16(acc[mf][nf], ah[mf], bl);
            }
        }
    }
    __syncthreads();   // X/W1 dead; H/W2 overlay begins

    // ---- stage W2 image via cp.async (overlaps tanh epilogue) ----
    {
        const char* src = (const char*)g_W2img[which];
        for (int i = tid; i < W2IMG_BYTES / 16; i += 128) {
            CPA16(smb + W2H_OFF + i * 16, src + i * 16);
        }
        CPA_COMMIT();
    }

    // ---- epilogue 1: h = tanh(acc) -> H hi/lo smem (C already inside) ----
    #pragma unroll
    for (int mf = 0; mf < 4; mf++) {
        int r_ = mf * 16 + lr;
        #pragma unroll
        for (int nf = 0; nf < 4; nf++) {
            int j = n0 + nf * 8 + lq * 2;
            float h0 = tanh_fast(acc[mf][nf][0]);
            float h1 = tanh_fast(acc[mf][nf][1]);
            float h2 = tanh_fast(acc[mf][nf][2]);
            float h3 = tanh_fast(acc[mf][nf][3]);
            sts_split(sm, HH_OFF + r_ * HSTR + j * 2,
                          HL_OFF + r_ * HSTR + j * 2, h0, h1);
            sts_split(sm, HH_OFF + (r_ + 8) * HSTR + j * 2,
                          HL_OFF + (r_ + 8) * HSTR + j * 2, h2, h3);
        }
    }
    CPA_WAIT0();
    __syncthreads();

    // ---- GEMM2: per warp M16 (r0=wid*16) x N32 x K128 ----
    float acc2[4][4];
    #pragma unroll
    for (int a = 0; a < 4; a++)
        #pragma unroll
        for (int b = 0; b < 4; b++) acc2[a][b] = 0.0f;

    const int r0 = wid * 16;
    const uint32_t aLane2 = (uint32_t)((lane & 15) * HSTR + (lane >> 4) * 16);
    const uint32_t bLane2 = (uint32_t)((lane & 7) * W2STR + ((lane >> 3) & 1) * 16);

    #pragma unroll
    for (int kf = 0; kf < 8; kf++) {
        uint32_t ah[4], al[4];
        uint32_t abase = smb + r0 * HSTR + kf * 32 + aLane2;
        ldmx4(ah, abase + HH_OFF);
        ldmx4(al, abase + HL_OFF);
        #pragma unroll
        for (int nf = 0; nf < 4; nf++) {
            uint32_t bb = smb + nf * 8 * W2STR + kf * 32 + bLane2;
            uint32_t bh[2], bl[2];
            ldmx2(bh, bb + W2H_OFF);
            ldmx2(bl, bb + W2L_OFF);
            mma_bf16(acc2[nf], ah, bh);
            mma_bf16(acc2[nf], al, bh);
            mma_bf16(acc2[nf], ah, bl);
        }
    }

    // ---- epilogue 2: state += dt * (acc2 + b2) ----
    {
        float tfv = __ldg(tfin + (node_base >> 12));
        float dtv = fminf(fmaxf(tfv - tstart, 0.0f), dtmax);
        #pragma unroll
        for (int nf = 0; nf < 4; nf++) {
            int d_ = nf * 8 + lq * 2;
            float2 bv = *(const float2*)(b2 + d_);
            int r_ = r0 + lr;
            float* p0 = state + (size_t)(node_base + r_) * ROW + toff + d_;
            float2 cur = *(float2*)p0;
            cur.x += dtv * (acc2[nf][0] + bv.x);
            cur.y += dtv * (acc2[nf][1] + bv.y);
            *(float2*)p0 = cur;
            float* p1 = state + (size_t)(node_base + r_ + 8) * ROW + toff + d_;
            cur = *(float2*)p1;
            cur.x += dtv * (acc2[nf][2] + bv.x);
            cur.y += dtv * (acc2[nf][3] + bv.y);
            *(float2*)p1 = cur;
        }
    }
}

extern "C" void kernel_launch(void* const* d_in, const int* in_sizes, int n_in,
                              void* d_out, int out_size)
{
    const float* x    = (const float*)d_in[0];
    const float* tf   = (const float*)d_in[1];
    const float* W1q  = (const float*)d_in[2];
    const float* b1q  = (const float*)d_in[3];
    const float* W2q  = (const float*)d_in[4];
    const float* b2q  = (const float*)d_in[5];
    const float* W1p  = (const float*)d_in[6];
    const float* b1p  = (const float*)d_in[7];
    const float* W2p  = (const float*)d_in[8];
    const float* b2p  = (const float*)d_in[9];
    float* state = (float*)d_out;

    cudaFuncSetAttribute(half_step_mma,
                         cudaFuncAttributeMaxDynamicSharedMemorySize, SMEM_BYTES);

    cudaMemcpyAsync(state, x, (size_t)out_size * sizeof(float),
                    cudaMemcpyDeviceToDevice);

    setup_weights<<<2, 128>>>(W1q, W2q, W1p, W2p);
    precompute_C_kernel<<<512, 128>>>(x, W1q, b1q, W1p, b1p);

    const float DT = 0.25f;

    for (int k = 0; k < 18; k++) {
        float tsq = (k == 0) ? 0.0f : (0.125f + (k - 1) * DT);
        float dmq = (k == 0) ? 0.125f : DT;
        half_step_mma<<<NCTA, 128, SMEM_BYTES>>>(
            state, tf, b2q, /*which=*/0,
            /*zoff=*/D, /*toff=*/0, tsq, dmq);

        float tsp = k * DT;
        half_step_mma<<<NCTA, 128, SMEM_BYTES>>>(
            state, tf, b2p, /*which=*/1,
            /*zoff=*/0, /*toff=*/D, tsp, DT);
    }
    (void)in_sizes; (void)n_in;
}